// round 5
// baseline (speedup 1.0000x reference)
#include <cuda_runtime.h>
#include <cstdint>

// ALiBi_33981781246374: out[b,h,i,j] = sum_d q[b,h,i,d]*hs[h]/sqrt(D) * k[b,h,j,d]
//                                      - slopes[h]*(pos[tok[b,i]] - pos[tok[b,j]])
// B=2, H=16, S=2048, D=128. Output fp32 [B,H,S,S].
//
// Per-(b,h) GEMM, 128(i) x 256(j) CTA tiles, D=128 fully SMEM-resident.
// Tile prologue is pure cp.async (LDGSTS, no data registers). The per-head
// q scale is applied to the ACCUMULATOR in the epilogue (uniform per CTA),
// fused with the ALiBi bias: out = fma(acc, qscale, -slope*pos_i) + slope*pos_j.
// 8 warps in a 2x4 grid of 64x64 warp tiles: 4 m16-tiles x 8 n8-tiles each,
// tf32 mma.sync.m16n8k8 (fp32 accum) — warp shape minimizes smem-crossbar
// bytes/FLOP. Streaming stores keep the write-once output out of L2's way.

#define S_DIM 2048
#define D_DIM 128
#define H_DIM 16
#define TILE_I 128
#define TILE_J 256
#define SSTRIDE 132   // pad: fragment word bank = 4g+t, bijective 0..31 -> conflict-free

extern __shared__ float smem[];

__device__ __forceinline__ void cp_async16(float* dst_smem, const float* src_gmem) {
    uint32_t d = (uint32_t)__cvta_generic_to_shared(dst_smem);
    asm volatile("cp.async.cg.shared.global [%0], [%1], 16;\n"
                 :: "r"(d), "l"(src_gmem));
}

__global__ void __launch_bounds__(256, 1)
alibi_scores_kernel(const float* __restrict__ q,
                    const float* __restrict__ k,
                    const float* __restrict__ head_scales,
                    const float* __restrict__ slopes,
                    const float* __restrict__ positions,
                    const int*   __restrict__ token_indices,
                    float* __restrict__ out)
{
    float* Qs  = smem;                         // 128 x 132
    float* Ks  = smem + TILE_I * SSTRIDE;      // 256 x 132
    float* spi = Ks   + TILE_J * SSTRIDE;      // 128  (slope * pos_i)
    float* spj = spi  + TILE_I;                // 256  (slope * pos_j)

    const int tid = threadIdx.x;
    const int z   = blockIdx.z;                // b*H + h (matches out layout)
    const int b   = z >> 4;
    const int h   = z & 15;
    const int i0  = blockIdx.y * TILE_I;
    const int j0  = blockIdx.x * TILE_J;

    const float qscale = head_scales[h] * 0.08838834764831845f; // hs/sqrt(128)
    const float slope  = slopes[h];

    const float* qg = q + ((size_t)z * S_DIM + i0) * D_DIM;
    const float* kg = k + ((size_t)z * S_DIM + j0) * D_DIM;

    // Q tile: 128 rows x 32 float4 -> 16 cp.async iters of 256 threads.
    #pragma unroll
    for (int it = 0; it < 16; ++it) {
        int idx = tid + it * 256;
        int r   = idx >> 5;
        int c4  = idx & 31;
        cp_async16(Qs + r * SSTRIDE + c4 * 4, qg + (size_t)r * D_DIM + c4 * 4);
    }
    // K tile: 256 rows x 32 float4 -> 32 cp.async iters.
    #pragma unroll
    for (int it = 0; it < 32; ++it) {
        int idx = tid + it * 256;
        int r   = idx >> 5;
        int c4  = idx & 31;
        cp_async16(Ks + r * SSTRIDE + c4 * 4, kg + (size_t)r * D_DIM + c4 * 4);
    }
    asm volatile("cp.async.commit_group;\n" ::: "memory");

    if (tid < TILE_I)
        spi[tid] = slope * positions[token_indices[b * S_DIM + i0 + tid]];
    spj[tid] = slope * positions[token_indices[b * S_DIM + j0 + tid]]; // all 256

    asm volatile("cp.async.wait_group 0;\n" ::: "memory");
    __syncthreads();

    // 8 warps = 2 (rows) x 4 (cols); warp tile 64(i) x 64(j).
    const int lane = tid & 31;
    const int warp = tid >> 5;
    const int wrow = (warp >> 2) * 64;   // 0 or 64
    const int wcol = (warp & 3) * 64;    // 0,64,128,192
    const int g = lane >> 2;             // groupID (row within m16/n8 tile)
    const int t = lane & 3;              // threadID in group

    float acc[4][8][4];
    #pragma unroll
    for (int m = 0; m < 4; ++m)
        #pragma unroll
        for (int n = 0; n < 8; ++n)
            #pragma unroll
            for (int r = 0; r < 4; ++r) acc[m][n][r] = 0.f;

    #pragma unroll
    for (int k0 = 0; k0 < D_DIM; k0 += 8) {
        uint32_t af[4][4];
        #pragma unroll
        for (int m = 0; m < 4; ++m) {
            const float* a = Qs + (wrow + m * 16 + g) * SSTRIDE + k0 + t;
            af[m][0] = __float_as_uint(a[0]);       // A(g,   t)
            af[m][2] = __float_as_uint(a[4]);       // A(g,   t+4)
            const float* a8 = a + 8 * SSTRIDE;
            af[m][1] = __float_as_uint(a8[0]);      // A(g+8, t)
            af[m][3] = __float_as_uint(a8[4]);      // A(g+8, t+4)
        }
        uint32_t bf[8][2];
        #pragma unroll
        for (int n = 0; n < 8; ++n) {
            const float* bb = Ks + (wcol + n * 8 + g) * SSTRIDE + k0 + t;
            bf[n][0] = __float_as_uint(bb[0]);      // B(k=t,   n=g)
            bf[n][1] = __float_as_uint(bb[4]);      // B(k=t+4, n=g)
        }
        #pragma unroll
        for (int m = 0; m < 4; ++m)
            #pragma unroll
            for (int n = 0; n < 8; ++n)
                asm volatile(
                    "mma.sync.aligned.m16n8k8.row.col.f32.tf32.tf32.f32 "
                    "{%0,%1,%2,%3}, {%4,%5,%6,%7}, {%8,%9}, {%0,%1,%2,%3};\n"
                    : "+f"(acc[m][n][0]), "+f"(acc[m][n][1]),
                      "+f"(acc[m][n][2]), "+f"(acc[m][n][3])
                    : "r"(af[m][0]), "r"(af[m][1]), "r"(af[m][2]), "r"(af[m][3]),
                      "r"(bf[n][0]), "r"(bf[n][1]));
    }

    // Epilogue: out = fma(acc, qscale, -spi) + spj. Streaming stores.
    float* outp = out + (size_t)z * S_DIM * S_DIM;
    #pragma unroll
    for (int m = 0; m < 4; ++m) {
        int r0 = wrow + m * 16 + g;
        float pi0 = spi[r0];
        float pi1 = spi[r0 + 8];
        #pragma unroll
        for (int n = 0; n < 8; ++n) {
            int c = wcol + n * 8 + t * 2;
            float pj0 = spj[c];
            float pj1 = spj[c + 1];
            float2 v0 = make_float2(fmaf(acc[m][n][0], qscale, -pi0) + pj0,
                                    fmaf(acc[m][n][1], qscale, -pi0) + pj1);
            __stcs(reinterpret_cast<float2*>(outp + (size_t)(i0 + r0) * S_DIM + (j0 + c)), v0);
            float2 v1 = make_float2(fmaf(acc[m][n][2], qscale, -pi1) + pj0,
                                    fmaf(acc[m][n][3], qscale, -pi1) + pj1);
            __stcs(reinterpret_cast<float2*>(outp + (size_t)(i0 + r0 + 8) * S_DIM + (j0 + c)), v1);
        }
    }
}

extern "C" void kernel_launch(void* const* d_in, const int* in_sizes, int n_in,
                              void* d_out, int out_size)
{
    const float* q   = (const float*)d_in[0];
    const float* k   = (const float*)d_in[1];
    const float* hs  = (const float*)d_in[2];
    const float* sl  = (const float*)d_in[3];
    const float* pos = (const float*)d_in[4];
    const int*   tok = (const int*)d_in[5];
    float* out = (float*)d_out;

    // (128+256)*132 floats + (128+256) floats = 204288 bytes
    const size_t smem_bytes =
        ((size_t)(TILE_I + TILE_J) * SSTRIDE + (TILE_I + TILE_J)) * sizeof(float);
    cudaFuncSetAttribute(alibi_scores_kernel,
                         cudaFuncAttributeMaxDynamicSharedMemorySize,
                         (int)smem_bytes);

    dim3 grid(S_DIM / TILE_J, S_DIM / TILE_I, 2 * H_DIM);  // (8, 16, 32)
    dim3 block(256);
    alibi_scores_kernel<<<grid, block, smem_bytes>>>(q, k, hs, sl, pos, tok, out);
}

// round 6
// speedup vs baseline: 1.0017x; 1.0017x over previous
#include <cuda_runtime.h>
#include <cstdint>

// ALiBi_33981781246374: out[b,h,i,j] = sum_d q[b,h,i,d]*hs[h]/sqrt(D) * k[b,h,j,d]
//                                      - slopes[h]*(pos[tok[b,i]] - pos[tok[b,j]])
// B=2, H=16, S=2048, D=128. Output fp32 [B,H,S,S].
//
// R5 measured 283us with occ=12.3%, tensor=40%: 1 CTA/SM serialized
// tile-load -> barrier -> mainloop each wave. This version pipelines the
// cp.async tile load in 4 D-chunks (32 cols): compute on chunk c overlaps the
// loads of chunks c+1.., hiding the ~3.8us/wave load latency behind the MMAs.
// Mainloop/epilogue otherwise identical to R5 (tensor-busy calibrated 114us).

#define S_DIM 2048
#define D_DIM 128
#define H_DIM 16
#define TILE_I 128
#define TILE_J 256
#define SSTRIDE 132   // pad: fragment word bank = 4g+t, bijective 0..31 -> conflict-free

extern __shared__ float smem[];

__device__ __forceinline__ void cp_async16(float* dst_smem, const float* src_gmem) {
    uint32_t d = (uint32_t)__cvta_generic_to_shared(dst_smem);
    asm volatile("cp.async.cg.shared.global [%0], [%1], 16;\n"
                 :: "r"(d), "l"(src_gmem));
}
template <int N>
__device__ __forceinline__ void cp_async_wait() {
    asm volatile("cp.async.wait_group %0;\n" :: "n"(N) : "memory");
}

__global__ void __launch_bounds__(256, 1)
alibi_scores_kernel(const float* __restrict__ q,
                    const float* __restrict__ k,
                    const float* __restrict__ head_scales,
                    const float* __restrict__ slopes,
                    const float* __restrict__ positions,
                    const int*   __restrict__ token_indices,
                    float* __restrict__ out)
{
    float* Qs  = smem;                         // 128 x 132
    float* Ks  = smem + TILE_I * SSTRIDE;      // 256 x 132
    float* spi = Ks   + TILE_J * SSTRIDE;      // 128  (slope * pos_i)
    float* spj = spi  + TILE_I;                // 256  (slope * pos_j)

    const int tid = threadIdx.x;
    const int z   = blockIdx.z;                // b*H + h (matches out layout)
    const int b   = z >> 4;
    const int h   = z & 15;
    const int i0  = blockIdx.y * TILE_I;
    const int j0  = blockIdx.x * TILE_J;

    const float qscale = head_scales[h] * 0.08838834764831845f; // hs/sqrt(128)
    const float slope  = slopes[h];

    const float* qg = q + ((size_t)z * S_DIM + i0) * D_DIM;
    const float* kg = k + ((size_t)z * S_DIM + j0) * D_DIM;

    // Issue the whole tile as 4 cp.async groups, one per 32-col D-chunk.
    // Chunk c: Q 128 rows x 8 float4  (1024 f4 -> 4 iters of 256 thr)
    //          K 256 rows x 8 float4  (2048 f4 -> 8 iters)
    #pragma unroll
    for (int c = 0; c < 4; ++c) {
        #pragma unroll
        for (int it = 0; it < 4; ++it) {
            int e  = tid + it * 256;
            int r  = e >> 3;
            int cc = e & 7;
            int col4 = c * 8 + cc;
            cp_async16(Qs + r * SSTRIDE + col4 * 4, qg + (size_t)r * D_DIM + col4 * 4);
        }
        #pragma unroll
        for (int it = 0; it < 8; ++it) {
            int e  = tid + it * 256;
            int r  = e >> 3;
            int cc = e & 7;
            int col4 = c * 8 + cc;
            cp_async16(Ks + r * SSTRIDE + col4 * 4, kg + (size_t)r * D_DIM + col4 * 4);
        }
        asm volatile("cp.async.commit_group;\n" ::: "memory");
    }

    if (tid < TILE_I)
        spi[tid] = slope * positions[token_indices[b * S_DIM + i0 + tid]];
    spj[tid] = slope * positions[token_indices[b * S_DIM + j0 + tid]]; // all 256

    // 8 warps = 2 (rows) x 4 (cols); warp tile 64(i) x 64(j).
    const int lane = tid & 31;
    const int warp = tid >> 5;
    const int wrow = (warp >> 2) * 64;   // 0 or 64
    const int wcol = (warp & 3) * 64;    // 0,64,128,192
    const int g = lane >> 2;             // groupID (row within m16/n8 tile)
    const int t = lane & 3;              // threadID in group

    float acc[4][8][4];
    #pragma unroll
    for (int m = 0; m < 4; ++m)
        #pragma unroll
        for (int n = 0; n < 8; ++n)
            #pragma unroll
            for (int r = 0; r < 4; ++r) acc[m][n][r] = 0.f;

    // Compute chunk c after its cp.async group lands; later chunks stream in
    // under the MMA shadow.
    #define MMA_CHUNK(CBASE)                                                     \
        _Pragma("unroll")                                                        \
        for (int k0 = (CBASE); k0 < (CBASE) + 32; k0 += 8) {                     \
            uint32_t af[4][4];                                                   \
            _Pragma("unroll")                                                    \
            for (int m = 0; m < 4; ++m) {                                        \
                const float* a = Qs + (wrow + m * 16 + g) * SSTRIDE + k0 + t;    \
                af[m][0] = __float_as_uint(a[0]);                                \
                af[m][2] = __float_as_uint(a[4]);                                \
                const float* a8 = a + 8 * SSTRIDE;                               \
                af[m][1] = __float_as_uint(a8[0]);                               \
                af[m][3] = __float_as_uint(a8[4]);                               \
            }                                                                    \
            uint32_t bf[8][2];                                                   \
            _Pragma("unroll")                                                    \
            for (int n = 0; n < 8; ++n) {                                        \
                const float* bb = Ks + (wcol + n * 8 + g) * SSTRIDE + k0 + t;    \
                bf[n][0] = __float_as_uint(bb[0]);                               \
                bf[n][1] = __float_as_uint(bb[4]);                               \
            }                                                                    \
            _Pragma("unroll")                                                    \
            for (int m = 0; m < 4; ++m)                                          \
                _Pragma("unroll")                                                \
                for (int n = 0; n < 8; ++n)                                      \
                    asm volatile(                                                \
                        "mma.sync.aligned.m16n8k8.row.col.f32.tf32.tf32.f32 "    \
                        "{%0,%1,%2,%3}, {%4,%5,%6,%7}, {%8,%9}, {%0,%1,%2,%3};\n"\
                        : "+f"(acc[m][n][0]), "+f"(acc[m][n][1]),                \
                          "+f"(acc[m][n][2]), "+f"(acc[m][n][3])                 \
                        : "r"(af[m][0]), "r"(af[m][1]),                          \
                          "r"(af[m][2]), "r"(af[m][3]),                          \
                          "r"(bf[n][0]), "r"(bf[n][1]));                         \
        }

    cp_async_wait<3>(); __syncthreads(); MMA_CHUNK(0)
    cp_async_wait<2>(); __syncthreads(); MMA_CHUNK(32)
    cp_async_wait<1>(); __syncthreads(); MMA_CHUNK(64)
    cp_async_wait<0>(); __syncthreads(); MMA_CHUNK(96)
    #undef MMA_CHUNK

    // Epilogue: out = fma(acc, qscale, -spi) + spj. Streaming stores.
    float* outp = out + (size_t)z * S_DIM * S_DIM;
    #pragma unroll
    for (int m = 0; m < 4; ++m) {
        int r0 = wrow + m * 16 + g;
        float pi0 = spi[r0];
        float pi1 = spi[r0 + 8];
        #pragma unroll
        for (int n = 0; n < 8; ++n) {
            int c = wcol + n * 8 + t * 2;
            float pj0 = spj[c];
            float pj1 = spj[c + 1];
            float2 v0 = make_float2(fmaf(acc[m][n][0], qscale, -pi0) + pj0,
                                    fmaf(acc[m][n][1], qscale, -pi0) + pj1);
            __stcs(reinterpret_cast<float2*>(outp + (size_t)(i0 + r0) * S_DIM + (j0 + c)), v0);
            float2 v1 = make_float2(fmaf(acc[m][n][2], qscale, -pi1) + pj0,
                                    fmaf(acc[m][n][3], qscale, -pi1) + pj1);
            __stcs(reinterpret_cast<float2*>(outp + (size_t)(i0 + r0 + 8) * S_DIM + (j0 + c)), v1);
        }
    }
}

extern "C" void kernel_launch(void* const* d_in, const int* in_sizes, int n_in,
                              void* d_out, int out_size)
{
    const float* q   = (const float*)d_in[0];
    const float* k   = (const float*)d_in[1];
    const float* hs  = (const float*)d_in[2];
    const float* sl  = (const float*)d_in[3];
    const float* pos = (const float*)d_in[4];
    const int*   tok = (const int*)d_in[5];
    float* out = (float*)d_out;

    // (128+256)*132 floats + (128+256) floats = 204288 bytes
    const size_t smem_bytes =
        ((size_t)(TILE_I + TILE_J) * SSTRIDE + (TILE_I + TILE_J)) * sizeof(float);
    cudaFuncSetAttribute(alibi_scores_kernel,
                         cudaFuncAttributeMaxDynamicSharedMemorySize,
                         (int)smem_bytes);

    dim3 grid(S_DIM / TILE_J, S_DIM / TILE_I, 2 * H_DIM);  // (8, 16, 32)
    dim3 block(256);
    alibi_scores_kernel<<<grid, block, smem_bytes>>>(q, k, hs, sl, pos, tok, out);
}

// round 16
// speedup vs baseline: 1.3606x; 1.3583x over previous
#include <cuda_runtime.h>
#include <cuda_bf16.h>
#include <cstdint>

// ALiBi_33981781246374: out[b,h,i,j] = sum_d q[b,h,i,d]*hs[h]/sqrt(D) * k[b,h,j,d]
//                                      - slopes[h]*(pos[tok[b,i]] - pos[tok[b,j]])
// B=2, H=16, S=2048, D=128. Output fp32 [B,H,S,S].
//
// bf16 rewrite of the R5-R7 line (tf32 passed at rel_err 4.4e-6; bf16 costs
// 3 mantissa bits -> ~3e-5, threshold 1e-3). m16n8k16 bf16 HMMA: 2x tensor
// throughput AND 2x fewer LDS per FLOP vs tf32 k8 — strictly better under
// both live bottleneck theories (tensor-pipe cap / latency starvation).
// 512 threads (16 warps, 4/SMSP) kept from R7 for latency hiding.
// Q pre-scaled in fp32, converted to bf16 in the prologue; K converted raw.
// Smem: bf16 tiles with 68-word row stride (bank = 4g+t, conflict-free).

#define S_DIM 2048
#define D_DIM 128
#define H_DIM 16
#define TILE_I 128
#define TILE_J 256
#define SW 68   // row stride in 32-bit words (64 data words + 4 pad); 68%32=4

extern __shared__ uint32_t smem_u[];

__global__ void __launch_bounds__(512, 1)
alibi_scores_kernel(const float* __restrict__ q,
                    const float* __restrict__ k,
                    const float* __restrict__ head_scales,
                    const float* __restrict__ slopes,
                    const float* __restrict__ positions,
                    const int*   __restrict__ token_indices,
                    float* __restrict__ out)
{
    uint32_t* Qs = smem_u;                     // 128 rows x 68 words (bf16 pairs)
    uint32_t* Ks = smem_u + TILE_I * SW;       // 256 rows x 68 words
    float*   spi = (float*)(Ks + TILE_J * SW); // 128  (slope * pos_i)
    float*   spj = spi + TILE_I;               // 256  (slope * pos_j)

    const int tid = threadIdx.x;
    const int z   = blockIdx.z;                // b*H + h (matches out layout)
    const int b   = z >> 4;
    const int h   = z & 15;
    const int i0  = blockIdx.y * TILE_I;
    const int j0  = blockIdx.x * TILE_J;

    const float qscale = head_scales[h] * 0.08838834764831845f; // hs/sqrt(128)
    const float slope  = slopes[h];

    const float* qg = q + ((size_t)z * S_DIM + i0) * D_DIM;
    const float* kg = k + ((size_t)z * S_DIM + j0) * D_DIM;

    // Q tile: 128 rows x 32 float4 = 4096 f4 -> 8 iters of 512 threads.
    // fp32*qscale -> bf16x2 pairs (low = even k, high = odd k).
    #pragma unroll
    for (int it = 0; it < 8; ++it) {
        int idx = tid + it * 512;
        int r   = idx >> 5;
        int c4  = idx & 31;
        float4 v = reinterpret_cast<const float4*>(qg + (size_t)r * D_DIM)[c4];
        __nv_bfloat162* dst = reinterpret_cast<__nv_bfloat162*>(Qs + r * SW + c4 * 2);
        dst[0] = __floats2bfloat162_rn(v.x * qscale, v.y * qscale);
        dst[1] = __floats2bfloat162_rn(v.z * qscale, v.w * qscale);
    }
    // K tile: 256 rows x 32 float4 = 8192 f4 -> 16 iters.
    #pragma unroll
    for (int it = 0; it < 16; ++it) {
        int idx = tid + it * 512;
        int r   = idx >> 5;
        int c4  = idx & 31;
        float4 v = reinterpret_cast<const float4*>(kg + (size_t)r * D_DIM)[c4];
        __nv_bfloat162* dst = reinterpret_cast<__nv_bfloat162*>(Ks + r * SW + c4 * 2);
        dst[0] = __floats2bfloat162_rn(v.x, v.y);
        dst[1] = __floats2bfloat162_rn(v.z, v.w);
    }

    if (tid < TILE_I)
        spi[tid] = slope * positions[token_indices[b * S_DIM + i0 + tid]];
    if (tid < TILE_J)
        spj[tid] = slope * positions[token_indices[b * S_DIM + j0 + tid]];
    __syncthreads();

    // 16 warps = 4 (rows) x 4 (cols); warp tile 32(i) x 64(j).
    // Per warp: 2 m16-tiles x 8 n8-tiles, k=128 in 8 steps of k16 (bf16).
    const int lane = tid & 31;
    const int warp = tid >> 5;
    const int wrow = (warp >> 2) * 32;   // 0,32,64,96
    const int wcol = (warp & 3) * 64;    // 0,64,128,192
    const int g = lane >> 2;             // groupID
    const int t = lane & 3;              // threadID in group

    float acc[2][8][4];
    #pragma unroll
    for (int m = 0; m < 2; ++m)
        #pragma unroll
        for (int n = 0; n < 8; ++n)
            #pragma unroll
            for (int r = 0; r < 4; ++r) acc[m][n][r] = 0.f;

    #pragma unroll
    for (int kw = 0; kw < D_DIM / 2; kw += 8) {   // word index; k0 = 2*kw
        uint32_t af[2][4];
        #pragma unroll
        for (int m = 0; m < 2; ++m) {
            const uint32_t* a = Qs + (wrow + m * 16 + g) * SW + kw + t;
            af[m][0] = a[0];            // A[g   ][k0+2t, +1]
            af[m][2] = a[4];            // A[g   ][k0+8+2t, +1]
            const uint32_t* a8 = a + 8 * SW;
            af[m][1] = a8[0];           // A[g+8 ][k0+2t, +1]
            af[m][3] = a8[4];           // A[g+8 ][k0+8+2t, +1]
        }
        uint32_t bf[8][2];
        #pragma unroll
        for (int n = 0; n < 8; ++n) {
            const uint32_t* bb = Ks + (wcol + n * 8 + g) * SW + kw + t;
            bf[n][0] = bb[0];           // B[n=g][k0+2t, +1]
            bf[n][1] = bb[4];           // B[n=g][k0+8+2t, +1]
        }
        #pragma unroll
        for (int m = 0; m < 2; ++m)
            #pragma unroll
            for (int n = 0; n < 8; ++n)
                asm volatile(
                    "mma.sync.aligned.m16n8k16.row.col.f32.bf16.bf16.f32 "
                    "{%0,%1,%2,%3}, {%4,%5,%6,%7}, {%8,%9}, {%0,%1,%2,%3};\n"
                    : "+f"(acc[m][n][0]), "+f"(acc[m][n][1]),
                      "+f"(acc[m][n][2]), "+f"(acc[m][n][3])
                    : "r"(af[m][0]), "r"(af[m][1]), "r"(af[m][2]), "r"(af[m][3]),
                      "r"(bf[n][0]), "r"(bf[n][1]));
    }

    // Epilogue: out = acc - spi + spj (q already scaled). Streaming stores.
    float* outp = out + (size_t)z * S_DIM * S_DIM;
    #pragma unroll
    for (int m = 0; m < 2; ++m) {
        int r0 = wrow + m * 16 + g;
        float pi0 = spi[r0];
        float pi1 = spi[r0 + 8];
        #pragma unroll
        for (int n = 0; n < 8; ++n) {
            int c = wcol + n * 8 + t * 2;
            float pj0 = spj[c];
            float pj1 = spj[c + 1];
            float2 v0 = make_float2((acc[m][n][0] - pi0) + pj0,
                                    (acc[m][n][1] - pi0) + pj1);
            __stcs(reinterpret_cast<float2*>(outp + (size_t)(i0 + r0) * S_DIM + (j0 + c)), v0);
            float2 v1 = make_float2((acc[m][n][2] - pi1) + pj0,
                                    (acc[m][n][3] - pi1) + pj1);
            __stcs(reinterpret_cast<float2*>(outp + (size_t)(i0 + r0 + 8) * S_DIM + (j0 + c)), v1);
        }
    }
}

extern "C" void kernel_launch(void* const* d_in, const int* in_sizes, int n_in,
                              void* d_out, int out_size)
{
    const float* q   = (const float*)d_in[0];
    const float* k   = (const float*)d_in[1];
    const float* hs  = (const float*)d_in[2];
    const float* sl  = (const float*)d_in[3];
    const float* pos = (const float*)d_in[4];
    const int*   tok = (const int*)d_in[5];
    float* out = (float*)d_out;

    // (128+256)*68 words + 384 floats = 26496 words = 105984 bytes
    const size_t smem_bytes =
        ((size_t)(TILE_I + TILE_J) * SW + TILE_I + TILE_J) * 4;
    cudaFuncSetAttribute(alibi_scores_kernel,
                         cudaFuncAttributeMaxDynamicSharedMemorySize,
                         (int)smem_bytes);

    dim3 grid(S_DIM / TILE_J, S_DIM / TILE_I, 2 * H_DIM);  // (8, 16, 32)
    dim3 block(512);
    alibi_scores_kernel<<<grid, block, smem_bytes>>>(q, k, hs, sl, pos, tok, out);
}